// round 2
// baseline (speedup 1.0000x reference)
#include <cuda_runtime.h>
#include <cstdint>

// Motion loss on GB300: warp-per-(b,t), quaternion FK with pointer doubling.
//
// Inputs (metadata order): Y_m (64,2048,99) f32, X_m (64,2048,99) f32,
//                          Y_t (64,24,3) f32,   X_t (64,24,3) f32
// Output: scalar f32 loss.

namespace {

constexpr int J   = 24;
constexpr int TT  = 2048;
constexpr int BS  = 64;
constexpr int NBT = BS * TT;                 // 131072 (b,t) pairs
constexpr int WARPS_PER_BLOCK = 8;
constexpr int NBLOCKS = NBT / WARPS_PER_BLOCK; // 16384

// loss scales (B1 = B2 = 1, all joint weights = 1)
constexpr float S1 = 1.0f  / (float(NBT) * 96.0f);  // rot mse  (bs,T,24,4)
constexpr float S2 = 2.5f  / (float(NBT) * 72.0f);  // fk  mse  (bs,T,24,3) * 2.5
constexpr float S3 = 1.0f  / (float(NBT) * 3.0f);   // pos mse  (bs,T,3)

} // namespace

__device__ float g_partials[NBLOCKS];

__constant__ int c_parent[J] = {-1,0,0,0,1,2,3,4,5,6,7,8,9,9,9,12,13,14,16,17,18,19,20,21};

// q v q^-1 for unit q, then add parent translation: out = R(q)*v + t
__device__ __forceinline__ void qrot_add(
    float qw, float qx, float qy, float qz,
    float vx, float vy, float vz,
    float tx, float ty, float tz,
    float& ox, float& oy, float& oz)
{
    // t2 = 2 * cross(u, v)
    float t2x = 2.0f * (qy * vz - qz * vy);
    float t2y = 2.0f * (qz * vx - qx * vz);
    float t2z = 2.0f * (qx * vy - qy * vx);
    // v + w*t2 + cross(u, t2) + t
    ox = vx + qw * t2x + (qy * t2z - qz * t2y) + tx;
    oy = vy + qw * t2y + (qz * t2x - qx * t2z) + ty;
    oz = vz + qw * t2z + (qx * t2y - qy * t2x) + tz;
}

// Hamilton product r = p * c (w-first)
__device__ __forceinline__ void qmul(
    float pw, float px, float py, float pz,
    float cw, float cx, float cy, float cz,
    float& rw, float& rx, float& ry, float& rz)
{
    rw = pw * cw - px * cx - py * cy - pz * cz;
    rx = pw * cx + cw * px + (py * cz - pz * cy);
    ry = pw * cy + cw * py + (pz * cx - px * cz);
    rz = pw * cz + cw * pz + (px * cy - py * cx);
}

__global__ __launch_bounds__(WARPS_PER_BLOCK * 32)
void motion_loss_kernel(const float* __restrict__ Ym,
                        const float* __restrict__ Xm,
                        const float* __restrict__ Yt,
                        const float* __restrict__ Xt)
{
    const unsigned FULL = 0xffffffffu;
    const int lane = threadIdx.x & 31;
    const int wid  = threadIdx.x >> 5;
    const int gw   = blockIdx.x * WARPS_PER_BLOCK + wid;  // = b*2048 + t
    const int b    = gw >> 11;

    const size_t row = (size_t)gw * 99;

    // per-lane state: local transform (unit quat + translation) for X and Y
    float qxw = 1.f, qxx = 0.f, qxy = 0.f, qxz = 0.f;
    float qyw = 1.f, qyx = 0.f, qyy = 0.f, qyz = 0.f;
    float txx = 0.f, txy = 0.f, txz = 0.f;
    float tyx = 0.f, tyy = 0.f, tyz = 0.f;
    float acc = 0.f;
    int a = -1;

    if (lane < J) {
        a = c_parent[lane];

        const size_t qo = row + (size_t)(lane << 2);
        float rxw = Xm[qo + 0], rxx = Xm[qo + 1], rxy = Xm[qo + 2], rxz = Xm[qo + 3];
        float ryw = Ym[qo + 0], ryx = Ym[qo + 1], ryy = Ym[qo + 2], ryz = Ym[qo + 3];

        float inx = rsqrtf(rxw*rxw + rxx*rxx + rxy*rxy + rxz*rxz);
        float iny = rsqrtf(ryw*ryw + ryx*ryx + ryy*ryy + ryz*ryz);
        qxw = rxw * inx; qxx = rxx * inx; qxy = rxy * inx; qxz = rxz * inx;
        qyw = ryw * iny; qyx = ryx * iny; qyy = ryy * iny; qyz = ryz * iny;

        // rotation loss term (normalized quats, weight 1)
        float d0 = qxw - qyw, d1 = qxx - qyx, d2 = qxy - qyy, d3 = qxz - qyz;
        acc = S1 * (d0*d0 + d1*d1 + d2*d2 + d3*d3);

        if (lane == 0) {
            // root local translation = global position (raw, from the row tail)
            txx = Xm[row + 96]; txy = Xm[row + 97]; txz = Xm[row + 98];
            tyx = Ym[row + 96]; tyy = Ym[row + 97]; tyz = Ym[row + 98];
        } else {
            const int to = (b * J + lane) * 3;
            txx = Xt[to + 0]; txy = Xt[to + 1]; txz = Xt[to + 2];
            tyx = Yt[to + 0]; tyy = Yt[to + 1]; tyz = Yt[to + 2];
        }
    }

    // Pointer-doubling FK resolve: max depth 8 -> 4 steps (2^4 = 16 > 8).
    // Invariant: G_i = G_{a_i} o M_i  (G_{-1} = identity)
    #pragma unroll
    for (int step = 0; step < 4; ++step) {
        const int src = (a >= 0) ? a : lane;

        float pqxw = __shfl_sync(FULL, qxw, src);
        float pqxx = __shfl_sync(FULL, qxx, src);
        float pqxy = __shfl_sync(FULL, qxy, src);
        float pqxz = __shfl_sync(FULL, qxz, src);
        float ptxx = __shfl_sync(FULL, txx, src);
        float ptxy = __shfl_sync(FULL, txy, src);
        float ptxz = __shfl_sync(FULL, txz, src);

        float pqyw = __shfl_sync(FULL, qyw, src);
        float pqyx = __shfl_sync(FULL, qyx, src);
        float pqyy = __shfl_sync(FULL, qyy, src);
        float pqyz = __shfl_sync(FULL, qyz, src);
        float ptyx = __shfl_sync(FULL, tyx, src);
        float ptyy = __shfl_sync(FULL, tyy, src);
        float ptyz = __shfl_sync(FULL, tyz, src);

        int pa = __shfl_sync(FULL, a, src);

        if (a >= 0) {
            // M_i <- M_parentchunk o M_i :  t = R(pq)*t + pt ; q = pq * q
            float nx, ny, nz;
            qrot_add(pqxw, pqxx, pqxy, pqxz, txx, txy, txz, ptxx, ptxy, ptxz, nx, ny, nz);
            txx = nx; txy = ny; txz = nz;
            qmul(pqxw, pqxx, pqxy, pqxz, qxw, qxx, qxy, qxz, qxw, qxx, qxy, qxz);

            qrot_add(pqyw, pqyx, pqyy, pqyz, tyx, tyy, tyz, ptyx, ptyy, ptyz, nx, ny, nz);
            tyx = nx; tyy = ny; tyz = nz;
            qmul(pqyw, pqyx, pqyy, pqyz, qyw, qyx, qyy, qyz, qyw, qyx, qyy, qyz);

            a = pa;
        }
    }

    // global-translation loss; lane 0's gtr is exactly the raw position, so the
    // pos-MSE term folds in with weight S3.
    if (lane < J) {
        float dx = txx - tyx, dy = txy - tyy, dz = txz - tyz;
        float w = (lane == 0) ? (S2 + S3) : S2;
        acc += w * (dx*dx + dy*dy + dz*dz);
    }

    // warp reduce
    #pragma unroll
    for (int o = 16; o > 0; o >>= 1) acc += __shfl_xor_sync(FULL, acc, o);

    __shared__ float sh[WARPS_PER_BLOCK];
    if (lane == 0) sh[wid] = acc;
    __syncthreads();
    if (threadIdx.x == 0) {
        float s = 0.f;
        #pragma unroll
        for (int i = 0; i < WARPS_PER_BLOCK; ++i) s += sh[i];
        g_partials[blockIdx.x] = s;
    }
}

__global__ void reduce_kernel(float* __restrict__ out)
{
    __shared__ double sh[256];
    double s = 0.0;
    for (int i = threadIdx.x; i < NBLOCKS; i += 256) s += (double)g_partials[i];
    sh[threadIdx.x] = s;
    __syncthreads();
    #pragma unroll
    for (int o = 128; o > 0; o >>= 1) {
        if (threadIdx.x < o) sh[threadIdx.x] += sh[threadIdx.x + o];
        __syncthreads();
    }
    if (threadIdx.x == 0) out[0] = (float)sh[0];
}

extern "C" void kernel_launch(void* const* d_in, const int* in_sizes, int n_in,
                              void* d_out, int out_size)
{
    (void)in_sizes; (void)n_in; (void)out_size;
    const float* Ym = (const float*)d_in[0];
    const float* Xm = (const float*)d_in[1];
    const float* Yt = (const float*)d_in[2];
    const float* Xt = (const float*)d_in[3];

    motion_loss_kernel<<<NBLOCKS, WARPS_PER_BLOCK * 32>>>(Ym, Xm, Yt, Xt);
    reduce_kernel<<<1, 256>>>((float*)d_out);
}

// round 3
// speedup vs baseline: 2.1140x; 2.1140x over previous
#include <cuda_runtime.h>
#include <cstdint>

// Motion loss on GB300: thread-per-(b,t), serial quaternion FK over explicit
// chains, shared-memory staged coalesced loads, fused last-block reduction.
//
// Inputs: Y_m (64,2048,99) f32, X_m (64,2048,99) f32,
//         Y_t (64,24,3) f32,   X_t (64,24,3) f32
// Output: scalar f32 loss.

namespace {

constexpr int ROW  = 99;                      // floats per (b,t) row
constexpr int RPB  = 128;                     // rows (= threads) per block
constexpr int NBT  = 64 * 2048;               // 131072 rows
constexpr int NBLK = NBT / RPB;               // 1024 blocks
constexpr int ROW_F4 = RPB * ROW / 4;         // 3168 float4 per array per block
constexpr int SMEM_BYTES = 2 * RPB * ROW * 4; // 101376 B

constexpr float S1 = 1.0f / (float(NBT) * 96.0f);  // rot mse
constexpr float S2 = 2.5f / (float(NBT) * 72.0f);  // fk  mse * 2.5
constexpr float S3 = 1.0f / (float(NBT) * 3.0f);   // pos mse

} // namespace

__device__ float    g_partials[NBLK];
__device__ unsigned g_count = 0;

struct Xf { float qw, qx, qy, qz, tx, ty, tz; };

__device__ __forceinline__ void qnorm(float& w, float& x, float& y, float& z) {
    float inv = rsqrtf(w*w + x*x + y*y + z*z);
    w *= inv; x *= inv; y *= inv; z *= inv;
}

// child = parent o (local quat l, bone b); alias-safe (temps then store)
__device__ __forceinline__ void compose(const Xf& p,
                                        float lw, float lx, float ly, float lz,
                                        float bx, float by, float bz, Xf& o) {
    float t2x = 2.f * (p.qy * bz - p.qz * by);
    float t2y = 2.f * (p.qz * bx - p.qx * bz);
    float t2z = 2.f * (p.qx * by - p.qy * bx);
    float ntx = bx + p.qw * t2x + (p.qy * t2z - p.qz * t2y) + p.tx;
    float nty = by + p.qw * t2y + (p.qz * t2x - p.qx * t2z) + p.ty;
    float ntz = bz + p.qw * t2z + (p.qx * t2y - p.qy * t2x) + p.tz;
    float nqw = p.qw * lw - p.qx * lx - p.qy * ly - p.qz * lz;
    float nqx = p.qw * lx + lw * p.qx + (p.qy * lz - p.qz * ly);
    float nqy = p.qw * ly + lw * p.qy + (p.qz * lx - p.qx * lz);
    float nqz = p.qw * lz + lw * p.qz + (p.qx * ly - p.qy * lx);
    o.qw = nqw; o.qx = nqx; o.qy = nqy; o.qz = nqz;
    o.tx = ntx; o.ty = nty; o.tz = ntz;
}

// one non-root joint: rot loss + compose both skeletons + fk loss
__device__ __forceinline__ void jstep(const float* __restrict__ rx,
                                      const float* __restrict__ ry,
                                      int j,
                                      const float* __restrict__ tX,
                                      const float* __restrict__ tY,
                                      const Xf& pX, const Xf& pY,
                                      Xf& oX, Xf& oY, float& acc) {
    float xw = rx[4*j+0], xx = rx[4*j+1], xy = rx[4*j+2], xz = rx[4*j+3];
    float yw = ry[4*j+0], yx = ry[4*j+1], yy = ry[4*j+2], yz = ry[4*j+3];
    qnorm(xw, xx, xy, xz);
    qnorm(yw, yx, yy, yz);
    float d0 = xw - yw, d1 = xx - yx, d2 = xy - yy, d3 = xz - yz;
    acc += S1 * (d0*d0 + d1*d1 + d2*d2 + d3*d3);

    float bx = __ldg(tX + 3*j + 0), by = __ldg(tX + 3*j + 1), bz = __ldg(tX + 3*j + 2);
    float cx = __ldg(tY + 3*j + 0), cy = __ldg(tY + 3*j + 1), cz = __ldg(tY + 3*j + 2);
    compose(pX, xw, xx, xy, xz, bx, by, bz, oX);
    compose(pY, yw, yx, yy, yz, cx, cy, cz, oY);

    float ex = oX.tx - oY.tx, ey = oX.ty - oY.ty, ez = oX.tz - oY.tz;
    acc += S2 * (ex*ex + ey*ey + ez*ez);
}

__global__ __launch_bounds__(RPB, 2)
void motion_loss_kernel(const float* __restrict__ Ym,
                        const float* __restrict__ Xm,
                        const float* __restrict__ Yt,
                        const float* __restrict__ Xt,
                        float* __restrict__ out)
{
    extern __shared__ float sm[];
    float* sX = sm;
    float* sY = sm + RPB * ROW;

    const int tid = threadIdx.x;

    // ---- stage 128 rows of Xm and Ym, fully coalesced float4 ----
    {
        const float4* gx = (const float4*)(Xm + (size_t)blockIdx.x * RPB * ROW);
        const float4* gy = (const float4*)(Ym + (size_t)blockIdx.x * RPB * ROW);
        float4* dx = (float4*)sX;
        float4* dy = (float4*)sY;
        #pragma unroll
        for (int k = 0; k < 25; ++k) {
            int i = tid + k * RPB;
            if (i < ROW_F4) { dx[i] = gx[i]; dy[i] = gy[i]; }
        }
    }
    __syncthreads();

    const float* rx = sX + tid * ROW;
    const float* ry = sY + tid * ROW;

    const int b = (blockIdx.x * RPB) >> 11;       // 16 blocks per batch item
    const float* tX = Xt + b * 72;
    const float* tY = Yt + b * 72;

    float acc = 0.f;

    // ---- root (joint 0): global = local; pos loss folds in ----
    Xf X0, Y0;
    {
        float xw = rx[0], xx = rx[1], xy = rx[2], xz = rx[3];
        float yw = ry[0], yx = ry[1], yy = ry[2], yz = ry[3];
        qnorm(xw, xx, xy, xz);
        qnorm(yw, yx, yy, yz);
        float d0 = xw - yw, d1 = xx - yx, d2 = xy - yy, d3 = xz - yz;
        acc += S1 * (d0*d0 + d1*d1 + d2*d2 + d3*d3);
        X0.qw = xw; X0.qx = xx; X0.qy = xy; X0.qz = xz;
        Y0.qw = yw; Y0.qx = yx; Y0.qy = yy; Y0.qz = yz;
        X0.tx = rx[96]; X0.ty = rx[97]; X0.tz = rx[98];
        Y0.tx = ry[96]; Y0.ty = ry[97]; Y0.tz = ry[98];
        float ex = X0.tx - Y0.tx, ey = X0.ty - Y0.ty, ez = X0.tz - Y0.tz;
        acc += (S2 + S3) * (ex*ex + ey*ey + ez*ez);
    }

    Xf A, B;
    // chain 0 -> 1 -> 4 -> 7 -> 10
    jstep(rx, ry,  1, tX, tY, X0, Y0, A, B, acc);
    jstep(rx, ry,  4, tX, tY, A,  B,  A, B, acc);
    jstep(rx, ry,  7, tX, tY, A,  B,  A, B, acc);
    jstep(rx, ry, 10, tX, tY, A,  B,  A, B, acc);
    // chain 0 -> 2 -> 5 -> 8 -> 11
    jstep(rx, ry,  2, tX, tY, X0, Y0, A, B, acc);
    jstep(rx, ry,  5, tX, tY, A,  B,  A, B, acc);
    jstep(rx, ry,  8, tX, tY, A,  B,  A, B, acc);
    jstep(rx, ry, 11, tX, tY, A,  B,  A, B, acc);
    // chain 0 -> 3 -> 6 -> 9 (save G9)
    jstep(rx, ry,  3, tX, tY, X0, Y0, A, B, acc);
    jstep(rx, ry,  6, tX, tY, A,  B,  A, B, acc);
    jstep(rx, ry,  9, tX, tY, A,  B,  A, B, acc);
    Xf X9 = A, Y9 = B;
    // chain 9 -> 12 -> 15
    jstep(rx, ry, 12, tX, tY, X9, Y9, A, B, acc);
    jstep(rx, ry, 15, tX, tY, A,  B,  A, B, acc);
    // chain 9 -> 13 -> 16 -> 18 -> 20 -> 22
    jstep(rx, ry, 13, tX, tY, X9, Y9, A, B, acc);
    jstep(rx, ry, 16, tX, tY, A,  B,  A, B, acc);
    jstep(rx, ry, 18, tX, tY, A,  B,  A, B, acc);
    jstep(rx, ry, 20, tX, tY, A,  B,  A, B, acc);
    jstep(rx, ry, 22, tX, tY, A,  B,  A, B, acc);
    // chain 9 -> 14 -> 17 -> 19 -> 21 -> 23
    jstep(rx, ry, 14, tX, tY, X9, Y9, A, B, acc);
    jstep(rx, ry, 17, tX, tY, A,  B,  A, B, acc);
    jstep(rx, ry, 19, tX, tY, A,  B,  A, B, acc);
    jstep(rx, ry, 21, tX, tY, A,  B,  A, B, acc);
    jstep(rx, ry, 23, tX, tY, A,  B,  A, B, acc);

    // ---- block reduction (4 warps) ----
    const unsigned FULL = 0xffffffffu;
    #pragma unroll
    for (int o = 16; o > 0; o >>= 1) acc += __shfl_xor_sync(FULL, acc, o);

    __shared__ float wsum[4];
    __shared__ int   s_last;
    const int lane = tid & 31, wid = tid >> 5;
    if (lane == 0) wsum[wid] = acc;
    __syncthreads();

    if (tid == 0) {
        float s = wsum[0] + wsum[1] + wsum[2] + wsum[3];
        g_partials[blockIdx.x] = s;
        __threadfence();
        unsigned ticket = atomicAdd(&g_count, 1u);
        s_last = (ticket == NBLK - 1) ? 1 : 0;
    }
    __syncthreads();

    // ---- last block finishes: deterministic fixed-order final sum ----
    if (s_last) {
        double v = 0.0;
        #pragma unroll
        for (int k = 0; k < NBLK / RPB; ++k)      // 8 per thread
            v += (double)g_partials[tid + k * RPB];

        __shared__ double dsum[RPB];
        dsum[tid] = v;
        __syncthreads();
        #pragma unroll
        for (int o = RPB / 2; o > 0; o >>= 1) {
            if (tid < o) dsum[tid] += dsum[tid + o];
            __syncthreads();
        }
        if (tid == 0) {
            out[0] = (float)dsum[0];
            g_count = 0;                           // reset for next graph replay
        }
    }
}

extern "C" void kernel_launch(void* const* d_in, const int* in_sizes, int n_in,
                              void* d_out, int out_size)
{
    (void)in_sizes; (void)n_in; (void)out_size;
    const float* Ym = (const float*)d_in[0];
    const float* Xm = (const float*)d_in[1];
    const float* Yt = (const float*)d_in[2];
    const float* Xt = (const float*)d_in[3];

    cudaFuncSetAttribute(motion_loss_kernel,
                         cudaFuncAttributeMaxDynamicSharedMemorySize, SMEM_BYTES);
    motion_loss_kernel<<<NBLK, RPB, SMEM_BYTES>>>(Ym, Xm, Yt, Xt, (float*)d_out);
}